// round 17
// baseline (speedup 1.0000x reference)
#include <cuda_runtime.h>
#include <cuda_fp16.h>
#include <cstdint>

// OctreeConvBnRelu via warp-level mma.sync (HMMA fp16, f32 accum).
// Round 17: conv = R9 verbatim (the measured-best operating point:
// m16 x n64 warp tiles, 3-stage cp.async, 2 syncs/k, s_idx from raw neigh),
// with only zero-risk deltas: uint4-packed B fragments (8 LDS.128 instead of
// 16 LDS.64 per warp/k) and a trimmed launch tail (4 launches instead of 6).

#define DEVFN __device__ __forceinline__

DEVFN uint32_t smem_u32(const void* p) {
    uint32_t a;
    asm("{ .reg .u64 t; cvta.to.shared.u64 t, %1; cvt.u32.u64 %0, t; }" : "=r"(a) : "l"(p));
    return a;
}
DEVFN uint32_t pack_h2(float x, float y) {
    __half2 v = __halves2half2(__float2half_rn(x), __float2half_rn(y));  // x = low
    return *(uint32_t*)&v;
}
DEVFN void ldmatrix_x4(uint32_t* r, uint32_t addr) {
    asm volatile("ldmatrix.sync.aligned.m8n8.x4.shared.b16 {%0,%1,%2,%3}, [%4];"
                 : "=r"(r[0]), "=r"(r[1]), "=r"(r[2]), "=r"(r[3]) : "r"(addr));
}
DEVFN void mma_f16(float* d, const uint32_t* a, uint32_t b0, uint32_t b1) {
    asm volatile(
        "mma.sync.aligned.m16n8k16.row.col.f32.f16.f16.f32 "
        "{%0,%1,%2,%3}, {%4,%5,%6,%7}, {%8,%9}, {%0,%1,%2,%3};"
        : "+f"(d[0]), "+f"(d[1]), "+f"(d[2]), "+f"(d[3])
        : "r"(a[0]), "r"(a[1]), "r"(a[2]), "r"(a[3]), "r"(b0), "r"(b1));
}
DEVFN void cp_async16(uint32_t smem_dst, const void* gsrc) {
    asm volatile("cp.async.cg.shared.global [%0], [%1], 16;"
                 :: "r"(smem_dst), "l"(gsrc) : "memory");
}
#define CP_COMMIT() asm volatile("cp.async.commit_group;" ::: "memory")

// ------------------------- globals -------------------------
__device__ float g_sum[64];
__device__ float g_sumsq[64];
// B fragments: [27][ntile 8][lane 32] uint4 = {ks0.x, ks0.y, ks1.x, ks1.y} (4KB/k)
__device__ __align__(16) uint4 g_Bfrag4[27 * 256];
// fp16 data image: row = 32 half = 64B
static const int ROW_CAP = 301056;
__device__ __align__(16) uint8_t g_dataF16[(size_t)ROW_CAP * 64];
__device__ __align__(16) uint8_t g_zero_row[64];   // stays zero

// ------------------------- data prep: f32 row -> fp16 row -------------------------
__global__ __launch_bounds__(256) void prep_data_kernel(const float* __restrict__ data, int N) {
    int r = blockIdx.x * 256 + threadIdx.x;
    if (r >= N || r >= ROW_CAP) return;
    const float4* src = (const float4*)(data + (size_t)r * 32);
    uint32_t u[16];
    #pragma unroll
    for (int i = 0; i < 8; i++) {
        float4 v = src[i];
        u[2 * i]     = pack_h2(v.x, v.y);
        u[2 * i + 1] = pack_h2(v.z, v.w);
    }
    uint4* dst = (uint4*)(g_dataF16 + (size_t)r * 64);
    #pragma unroll
    for (int i = 0; i < 4; i++)
        dst[i] = make_uint4(u[4 * i], u[4 * i + 1], u[4 * i + 2], u[4 * i + 3]);
}

// ------------------------- weight prep (+ stats zero) -------------------------
// m16n8k16 B frag: lane l: reg0 = B[2q+{0,1}][g], reg1 = B[2q+8+{0,1}][g],
// q=l&3, g=l>>2. uint4 packs kstep0 (c0:16) and kstep1 (c16:32).
__global__ __launch_bounds__(256) void prep_weights_kernel(const float* __restrict__ weight) {
    int k = blockIdx.x;
    int t = threadIdx.x;
    if (k == 0 && t < 128) {
        if (t < 64) g_sum[t] = 0.0f; else g_sumsq[t - 64] = 0.0f;
    }
    int lane = t & 31;
    int nt = t >> 5;
    int q = lane & 3;
    int g = lane >> 2;
    int n = nt * 8 + g;
    const float* wk = weight + k * 2048;  // [32 c][64 o]

    uint4 v;
    v.x = pack_h2(wk[(2 * q) * 64 + n],      wk[(2 * q + 1) * 64 + n]);
    v.y = pack_h2(wk[(2 * q + 8) * 64 + n],  wk[(2 * q + 9) * 64 + n]);
    v.z = pack_h2(wk[(16 + 2 * q) * 64 + n], wk[(16 + 2 * q + 1) * 64 + n]);
    v.w = pack_h2(wk[(16 + 2 * q + 8) * 64 + n], wk[(16 + 2 * q + 9) * 64 + n]);
    g_Bfrag4[(k * 8 + nt) * 32 + lane] = v;
}

// ------------------------- conv kernel (R9 structure) -------------------------
// block = 128 nodes x 64 outs, 256 threads, 8 warps each one m16 tile x n64.
// dynamic smem: A 3x8KB + B 3x4KB = 36KB.
__global__ __launch_bounds__(256) void conv_kernel(
    const int* __restrict__ neigh,      // [N,27] int32 (raw layout)
    float* __restrict__ out,            // [N,64]
    int N)
{
    extern __shared__ __align__(256) uint8_t dyn[];
    const uint32_t aA = smem_u32(dyn);
    const uint32_t aB = aA + 3 * 8192;
    __shared__ int s_idx[27 * 128];
    __shared__ float red_sum[8 * 64];
    __shared__ float red_sq[8 * 64];

    const int tid = threadIdx.x;
    const int w = tid >> 5;
    const int lane = tid & 31;
    const int n0 = blockIdx.x * 128;

    // preload neighbor indices (coalesced: linear over the block's 27*128 ints)
    {
        const int* base = neigh + (size_t)n0 * 27;
        for (int e = tid; e < 27 * 128; e += 256) {
            int r = e / 27;
            int kk = e - r * 27;
            int v = (n0 + r < N) ? base[e] : -1;
            if ((unsigned)v >= (unsigned)N) v = -1;
            s_idx[kk * 128 + r] = v;
        }
    }
    __syncthreads();

    // A gather: thread t owns row t>>1, chunks j0 = (t&1)*2, j0+1 (32B of a row)
    const int grow = tid >> 1;
    const int j0 = (tid & 1) * 2;
    const uint32_t gsw = ((uint32_t)(grow >> 1) & 3);     // chunk xor for this row
    const uint32_t adst = (uint32_t)grow * 64;

    // ldmatrix relative offsets (ks = 0,1) for this warp's m16 tile
    uint32_t lm_rel[2];
    {
        uint32_t r = (uint32_t)(w * 16 + (lane & 15));
        uint32_t rx = (r >> 1) & 3;
        #pragma unroll
        for (int ks = 0; ks < 2; ks++) {
            uint32_t chunk = (uint32_t)(ks * 2 + (lane >> 4));
            lm_rel[ks] = r * 64 + ((chunk ^ rx) << 4);
        }
    }

    float acc[8][4];
    #pragma unroll
    for (int nt = 0; nt < 8; nt++)
        #pragma unroll
        for (int i = 0; i < 4; i++) acc[nt][i] = 0.0f;

    auto issue_stage = [&](int k, int s) {
        // B frags: 4KB contiguous, 1 chunk/thread
        cp_async16(aB + s * 4096 + tid * 16,
                   (const uint8_t*)g_Bfrag4 + (size_t)k * 4096 + tid * 16);
        // A: half a row per thread, idx from SMEM
        int idx = s_idx[k * 128 + grow];
        const uint8_t* src = (idx >= 0) ? g_dataF16 + (size_t)idx * 64
                                        : (const uint8_t*)g_zero_row;
        uint32_t db = aA + s * 8192 + adst;
        cp_async16(db + (((uint32_t)j0 ^ gsw) << 4),       src + j0 * 16);
        cp_async16(db + ((((uint32_t)j0 + 1) ^ gsw) << 4), src + j0 * 16 + 16);
        CP_COMMIT();
    };

    issue_stage(0, 0);
    issue_stage(1, 1);

    int s = 0;                 // stage of current k
    int s2 = 2;                // stage to fill next
    for (int k = 0; k < 27; k++) {
        if (k < 25) {
            issue_stage(k + 2, s2);
            asm volatile("cp.async.wait_group 2;" ::: "memory");
        } else if (k == 25) {
            asm volatile("cp.async.wait_group 1;" ::: "memory");
        } else {
            asm volatile("cp.async.wait_group 0;" ::: "memory");
        }
        __syncthreads();

        const uint32_t abase = aA + s * 8192;
        uint32_t af0[4], af1[4];
        ldmatrix_x4(af0, abase + lm_rel[0]);
        ldmatrix_x4(af1, abase + lm_rel[1]);

        // B: one LDS.128 per ntile (uint4 = both ksteps)
        const uint4* bbuf = (const uint4*)(dyn + 3 * 8192 + s * 4096);
        #pragma unroll
        for (int nt = 0; nt < 8; nt++) {
            uint4 bv = bbuf[nt * 32 + lane];
            mma_f16(acc[nt], af0, bv.x, bv.y);   // channels 0:16
            mma_f16(acc[nt], af1, bv.z, bv.w);   // channels 16:32
        }
        __syncthreads();   // readers done before this stage is refilled

        s = (s == 2) ? 0 : s + 1;
        s2 = (s2 == 2) ? 0 : s2 + 1;
    }

    // ---- epilogue ----
    // C fragment: lane: rows m0+g, m0+g+8; cols nt*8 + 2q, +1  (q=lane&3, g=lane>>2)
    const int q = lane & 3;
    const int g = lane >> 2;
    const int row0 = n0 + w * 16 + g;
    const int row1 = row0 + 8;

    if (row0 < N) {
        float* po = out + (size_t)row0 * 64 + 2 * q;
        #pragma unroll
        for (int nt = 0; nt < 8; nt++)
            *(float2*)(po + nt * 8) = make_float2(acc[nt][0], acc[nt][1]);
    }
    if (row1 < N) {
        float* po = out + (size_t)row1 * 64 + 2 * q;
        #pragma unroll
        for (int nt = 0; nt < 8; nt++)
            *(float2*)(po + nt * 8) = make_float2(acc[nt][2], acc[nt][3]);
    }

    // BN partials (invalid rows contributed exact zeros)
    float ps[16], pq[16];
    #pragma unroll
    for (int nt = 0; nt < 8; nt++) {
        ps[2 * nt]     = acc[nt][0] + acc[nt][2];
        ps[2 * nt + 1] = acc[nt][1] + acc[nt][3];
        pq[2 * nt]     = acc[nt][0] * acc[nt][0] + acc[nt][2] * acc[nt][2];
        pq[2 * nt + 1] = acc[nt][1] * acc[nt][1] + acc[nt][3] * acc[nt][3];
    }
    #pragma unroll
    for (int i = 0; i < 16; i++) {
        #pragma unroll
        for (int off = 4; off < 32; off <<= 1) {
            ps[i] += __shfl_xor_sync(0xffffffffu, ps[i], off);
            pq[i] += __shfl_xor_sync(0xffffffffu, pq[i], off);
        }
    }
    if (g == 0) {   // lanes 0..3 hold warp totals
        #pragma unroll
        for (int nt = 0; nt < 8; nt++) {
            int c = nt * 8 + 2 * q;
            red_sum[w * 64 + c]     = ps[2 * nt];
            red_sum[w * 64 + c + 1] = ps[2 * nt + 1];
            red_sq[w * 64 + c]      = pq[2 * nt];
            red_sq[w * 64 + c + 1]  = pq[2 * nt + 1];
        }
    }
    __syncthreads();
    if (tid < 64) {
        float t = 0.f;
        #pragma unroll
        for (int ww = 0; ww < 8; ww++) t += red_sum[ww * 64 + tid];
        atomicAdd(&g_sum[tid], t);
    } else if (tid < 128) {
        int c = tid - 64;
        float t = 0.f;
        #pragma unroll
        for (int ww = 0; ww < 8; ww++) t += red_sq[ww * 64 + c];
        atomicAdd(&g_sumsq[c], t);
    }
}

// ------------------------- BN+ReLU (finalize folded in) -------------------------
__global__ __launch_bounds__(256) void bn_relu_kernel(
    float* __restrict__ out,
    const float* __restrict__ gamma,
    const float* __restrict__ beta,
    float invN, int total4)
{
    __shared__ __align__(16) float s_sc[64];
    __shared__ __align__(16) float s_sh[64];
    int tid = threadIdx.x;
    if (tid < 64) {
        float mean = g_sum[tid] * invN;
        float var  = fmaxf(g_sumsq[tid] * invN - mean * mean, 0.0f);
        float sc   = gamma[tid] * rsqrtf(var + 1e-5f);
        s_sc[tid] = sc;
        s_sh[tid] = beta[tid] - mean * sc;
    }
    __syncthreads();

    int i = blockIdx.x * 256 + tid;
    if (i < total4) {
        float4 x = ((const float4*)out)[i];
        int cq = i & 15;
        float4 sc = ((const float4*)s_sc)[cq];
        float4 sh = ((const float4*)s_sh)[cq];
        float4 y;
        y.x = fmaxf(fmaf(x.x, sc.x, sh.x), 0.0f);
        y.y = fmaxf(fmaf(x.y, sc.y, sh.y), 0.0f);
        y.z = fmaxf(fmaf(x.z, sc.z, sh.z), 0.0f);
        y.w = fmaxf(fmaf(x.w, sc.w, sh.w), 0.0f);
        ((float4*)out)[i] = y;
    }
}

// ------------------------- launch -------------------------
extern "C" void kernel_launch(void* const* d_in, const int* in_sizes, int n_in,
                              void* d_out, int out_size)
{
    const float* data   = (const float*)d_in[0];   // [N,32]
    const int*   neigh  = (const int*)d_in[1];     // [N,27] int32
    const float* weight = (const float*)d_in[2];   // [27,32,64]
    const float* gamma  = (const float*)d_in[3];
    const float* beta   = (const float*)d_in[4];
    float* out = (float*)d_out;

    int N = in_sizes[0] / 32;

    // One-time opt-in: 36KB dynamic + ~18KB static > 48KB default.
    // Runs on the (uncaptured) correctness call; skipped during graph capture.
    static bool configured = false;
    if (!configured) {
        cudaFuncSetAttribute(conv_kernel,
                             cudaFuncAttributeMaxDynamicSharedMemorySize, 36864);
        configured = true;
    }

    prep_data_kernel<<<(N + 255) / 256, 256>>>(data, N);
    prep_weights_kernel<<<27, 256>>>(weight);
    conv_kernel<<<(N + 127) / 128, 256, 36864>>>(neigh, out, N);
    int total4 = N * 16;
    bn_relu_kernel<<<(total4 + 255) / 256, 256>>>(out, gamma, beta,
                                                  1.0f / (float)N, total4);
}